// round 7
// baseline (speedup 1.0000x reference)
#include <cuda_runtime.h>
#include <cstdint>

// Problem constants
#define NB    16
#define CD    256
#define HH    80
#define WW    60
#define LL    4800            // HH*WW
#define NHD   8
#define HDD   32
#define MR    (NB*LL)         // 76800 rows

#define EPI_NONE 0
#define EPI_ELU1 1
#define EPI_RELU 2

// ---------------- scratch (static device globals; no allocation) ----------------
__device__ float g_F0 [(size_t)MR * CD];   // exact x (residual/output; GEMM cvts A)
__device__ float g_F1 [(size_t)MR * CD];
__device__ float g_Q  [(size_t)MR * CD];
__device__ float g_K  [(size_t)MR * CD];
__device__ float g_V  [(size_t)MR * CD];
__device__ float g_PE [(size_t)CD * LL];
__device__ float g_KV [NB * NHD * HDD * HDD];
__device__ float g_KS [NB * NHD * HDD];
// tf32-rounded weights (original [K][N] layout)
__device__ float g_Wq[2 * CD * CD];
__device__ float g_Wk[2 * CD * CD];
__device__ float g_Wv[2 * CD * CD];
__device__ float g_Wm[2 * CD * CD];
__device__ float g_W1[2 * 2 * CD * CD];
__device__ float g_W2[2 * CD * CD];

__device__ __forceinline__ float rnd_tf32(float x) {
    float r;
    asm("cvt.rna.tf32.f32 %0, %1;" : "=f"(r) : "f"(x));
    return r;
}
__device__ __forceinline__ uint32_t f2tf(float x) {
    uint32_t u;
    asm("cvt.rna.tf32.f32 %0, %1;" : "=r"(u) : "f"(x));
    return u;
}

// ---------------- weight prep: round all weights to tf32 once ----------------
__global__ void weight_prep_kernel(
    const float* __restrict__ wq, const float* __restrict__ wk,
    const float* __restrict__ wv, const float* __restrict__ wm,
    const float* __restrict__ w1, const float* __restrict__ w2)
{
    int i = blockIdx.x * blockDim.x + threadIdx.x;
    const int S = 2 * CD * CD;
    if (i < S) g_Wq[i] = rnd_tf32(wq[i]);
    if (i < S) g_Wk[i] = rnd_tf32(wk[i]);
    if (i < S) g_Wv[i] = rnd_tf32(wv[i]);
    if (i < S) g_Wm[i] = rnd_tf32(wm[i]);
    if (i < S) g_W2[i] = rnd_tf32(w2[i]);
    if (i < 2 * S) g_W1[i] = rnd_tf32(w1[i]);
}

// ---------------- positional encoding ----------------
// fac = (-log(1e4)/256)//2 == -1.0  =>  div[j] = exp(-2*j)
__global__ void pe_precompute_kernel(float* __restrict__ PE) {
    int idx = blockIdx.x * blockDim.x + threadIdx.x;
    if (idx >= CD * LL) return;
    int c = idx / LL, l = idx % LL;
    int j = c >> 2, r = c & 3;
    int h = l / WW, w = l % WW;
    float f = expf(-2.0f * (float)j);
    float pos = (r < 2) ? (float)(w + 1) : (float)(h + 1);
    float arg = pos * f;
    PE[idx] = (r & 1) ? cosf(arg) : sinf(arg);
}

// NCHW -> [N,L,C] with PE add
__global__ void build_pe_kernel(const float* __restrict__ feat, const float* __restrict__ PE,
                                float* __restrict__ out) {
    __shared__ float tile[32][33];
    int n  = blockIdx.z;
    int c0 = blockIdx.y * 32;
    int l0 = blockIdx.x * 32;
    int tx = threadIdx.x, ty = threadIdx.y;
#pragma unroll
    for (int i = 0; i < 4; i++) {
        int c = c0 + ty + i * 8;
        int l = l0 + tx;
        tile[ty + i * 8][tx] = feat[((size_t)n * CD + c) * LL + l] + PE[(size_t)c * LL + l];
    }
    __syncthreads();
#pragma unroll
    for (int i = 0; i < 4; i++) {
        int l = l0 + ty + i * 8;
        int c = c0 + tx;
        out[((size_t)n * LL + l) * CD + c] = tile[tx][ty + i * 8];
    }
}

__global__ void unbuild_kernel(const float* __restrict__ in, float* __restrict__ out) {
    __shared__ float tile[32][33];
    int n  = blockIdx.z;
    int c0 = blockIdx.y * 32;
    int l0 = blockIdx.x * 32;
    int tx = threadIdx.x, ty = threadIdx.y;
#pragma unroll
    for (int i = 0; i < 4; i++) {
        int l = l0 + ty + i * 8;
        int c = c0 + tx;
        tile[ty + i * 8][tx] = in[((size_t)n * LL + l) * CD + c];
    }
    __syncthreads();
#pragma unroll
    for (int i = 0; i < 4; i++) {
        int c = c0 + ty + i * 8;
        int l = l0 + tx;
        out[((size_t)n * CD + c) * LL + l] = tile[tx][ty + i * 8];
    }
}

// ---------------- TF32 tensor-core GEMM (R3 core + 3-stage pipeline + A-cvt) ----------------
// C[M,N] = epi( [A|A2][M,Ktot] @ B[Ktot,N] ), row-major. B pre-rounded to tf32;
// A rounded at fragment load (cvt.rna.tf32). BM=BN=128, BK=16, 8 warps, m16n8k8.
#define APAD 20
#define BPAD 136
#define AS_W (128 * APAD)      // 2560 words per stage
#define BS_W (16 * BPAD)       // 2176 words per stage
#define STG  3
#define SMEM_BYTES (STG * (AS_W + BS_W) * 4)   // 56832

__device__ __forceinline__ void cp16(void* dst, const void* src) {
    uint32_t d = (uint32_t)__cvta_generic_to_shared(dst);
    asm volatile("cp.async.cg.shared.global [%0], [%1], 16;\n" :: "r"(d), "l"(src));
}

__global__ __launch_bounds__(256, 2) void tgemm_kernel(
    const float* __restrict__ A, const float* __restrict__ A2,
    const float* __restrict__ B, float* __restrict__ C,
    int M, int Ktot, int K1, int N, int epi)
{
    extern __shared__ float dsm[];

    int tid = threadIdx.x;
    int warp = tid >> 5;
    int lane = tid & 31;
    int g = lane >> 2;
    int q = lane & 3;
    int rowBase = blockIdx.y * 128;
    int colBase = blockIdx.x * 128;
    int wm0 = (warp >> 1) * 32;
    int wn0 = (warp & 1) * 64;
    int K2 = Ktot - K1;
    int NS = Ktot >> 4;

    float acc[2][8][4];
#pragma unroll
    for (int mt = 0; mt < 2; mt++)
#pragma unroll
        for (int nt = 0; nt < 8; nt++)
#pragma unroll
            for (int r = 0; r < 4; r++) acc[mt][nt][r] = 0.0f;

    // A chunks: c = tid, tid+256 ; row = c>>2, colc = c&3 (4 floats each)
    int aRow0 = tid >> 2,           aColc0 = tid & 3;
    int aRow1 = (tid + 256) >> 2,   aColc1 = (tid + 256) & 3;
    // B chunks: row = c>>5 (0..15), col = (c&31)*4
    int bRow0 = tid >> 5,           bCol0 = (tid & 31) << 2;
    int bRow1 = (tid + 256) >> 5;

    auto issue = [&](int kt, int buf) {
        float* Ad = dsm + buf * AS_W;
        float* Bd = dsm + STG * AS_W + buf * BS_W;
        int k0 = kt * 16;
        {
            int kk = k0 + aColc0 * 4;
            const float* src = (kk < K1) ? (A  + (size_t)(rowBase + aRow0) * K1 + kk)
                                         : (A2 + (size_t)(rowBase + aRow0) * K2 + (kk - K1));
            cp16(Ad + aRow0 * APAD + aColc0 * 4, src);
        }
        {
            int kk = k0 + aColc1 * 4;
            const float* src = (kk < K1) ? (A  + (size_t)(rowBase + aRow1) * K1 + kk)
                                         : (A2 + (size_t)(rowBase + aRow1) * K2 + (kk - K1));
            cp16(Ad + aRow1 * APAD + aColc1 * 4, src);
        }
        cp16(Bd + bRow0 * BPAD + bCol0, B + (size_t)(k0 + bRow0) * N + colBase + bCol0);
        cp16(Bd + bRow1 * BPAD + bCol0, B + (size_t)(k0 + bRow1) * N + colBase + bCol0);
    };

    issue(0, 0);
    asm volatile("cp.async.commit_group;\n");
    issue(1, 1);
    asm volatile("cp.async.commit_group;\n");

    for (int s = 0; s < NS; s++) {
        if (s + 1 < NS) asm volatile("cp.async.wait_group 1;\n");
        else            asm volatile("cp.async.wait_group 0;\n");
        __syncthreads();
        if (s + 2 < NS) {
            issue(s + 2, (s + 2) % STG);
            asm volatile("cp.async.commit_group;\n");
        }

        const float* AsB = dsm + (s % STG) * AS_W;
        const float* BsB = dsm + STG * AS_W + (s % STG) * BS_W;
#pragma unroll
        for (int ks = 0; ks < 2; ks++) {
            int kb = ks * 8;
            uint32_t af[2][4];
#pragma unroll
            for (int mt = 0; mt < 2; mt++) {
                int m = wm0 + mt * 16;
                af[mt][0] = f2tf(AsB[(m + g    ) * APAD + kb + q    ]);
                af[mt][1] = f2tf(AsB[(m + g + 8) * APAD + kb + q    ]);
                af[mt][2] = f2tf(AsB[(m + g    ) * APAD + kb + q + 4]);
                af[mt][3] = f2tf(AsB[(m + g + 8) * APAD + kb + q + 4]);
            }
            uint32_t bf[8][2];
#pragma unroll
            for (int nt = 0; nt < 8; nt++) {
                int n = wn0 + nt * 8 + g;
                bf[nt][0] = __float_as_uint(BsB[(kb + q    ) * BPAD + n]);
                bf[nt][1] = __float_as_uint(BsB[(kb + q + 4) * BPAD + n]);
            }
#pragma unroll
            for (int mt = 0; mt < 2; mt++)
#pragma unroll
                for (int nt = 0; nt < 8; nt++) {
                    asm volatile(
                        "mma.sync.aligned.m16n8k8.row.col.f32.tf32.tf32.f32 "
                        "{%0,%1,%2,%3}, {%4,%5,%6,%7}, {%8,%9}, {%0,%1,%2,%3};\n"
                        : "+f"(acc[mt][nt][0]), "+f"(acc[mt][nt][1]),
                          "+f"(acc[mt][nt][2]), "+f"(acc[mt][nt][3])
                        : "r"(af[mt][0]), "r"(af[mt][1]), "r"(af[mt][2]), "r"(af[mt][3]),
                          "r"(bf[nt][0]), "r"(bf[nt][1]));
                }
        }
    }

    // epilogue: c0,c1 -> (row g, col 2q), c2,c3 -> (row g+8, col 2q)
#pragma unroll
    for (int mt = 0; mt < 2; mt++) {
        int row = rowBase + wm0 + mt * 16 + g;
#pragma unroll
        for (int nt = 0; nt < 8; nt++) {
            int col = colBase + wn0 + nt * 8 + 2 * q;
            float v0 = acc[mt][nt][0], v1 = acc[mt][nt][1];
            float v2 = acc[mt][nt][2], v3 = acc[mt][nt][3];
            if (epi == EPI_ELU1) {
                v0 = (v0 > 0.f) ? v0 + 1.f : expf(v0);
                v1 = (v1 > 0.f) ? v1 + 1.f : expf(v1);
                v2 = (v2 > 0.f) ? v2 + 1.f : expf(v2);
                v3 = (v3 > 0.f) ? v3 + 1.f : expf(v3);
            } else if (epi == EPI_RELU) {
                v0 = fmaxf(v0, 0.f); v1 = fmaxf(v1, 0.f);
                v2 = fmaxf(v2, 0.f); v3 = fmaxf(v3, 0.f);
            }
            *(float2*)(C + (size_t)row * N + col)       = make_float2(v0, v1);
            *(float2*)(C + (size_t)(row + 8) * N + col) = make_float2(v2, v3);
        }
    }
}

// ---------------- KV = sum_s K[s,d] * v[s,e], Ksum per (n,h) ----------------
#define KV_CHUNKS 20
#define KV_SC (LL / KV_CHUNKS)
__global__ void kv_reduce_kernel(const float* __restrict__ Kb, const float* __restrict__ Vb,
                                 float* __restrict__ KV, float* __restrict__ KS) {
    int nh = blockIdx.x;
    int n = nh >> 3, h = nh & 7;
    int t = threadIdx.x;
    int d = t & 31;
    int eg = t >> 5;
    int s0 = blockIdx.y * KV_SC;
    float a0 = 0, a1 = 0, a2 = 0, a3 = 0, ks = 0;
    for (int s = s0; s < s0 + KV_SC; s++) {
        size_t base = ((size_t)(n * LL + s) * NHD + h) * HDD;
        float kd = Kb[base + d];
        float4 vv = *(const float4*)(Vb + base + eg * 4);
        a0 = fmaf(kd, vv.x, a0);
        a1 = fmaf(kd, vv.y, a1);
        a2 = fmaf(kd, vv.z, a2);
        a3 = fmaf(kd, vv.w, a3);
        ks += kd;
    }
    float* kvp = KV + ((size_t)nh * HDD + d) * HDD + eg * 4;
    atomicAdd(kvp + 0, a0);
    atomicAdd(kvp + 1, a1);
    atomicAdd(kvp + 2, a2);
    atomicAdd(kvp + 3, a3);
    if (eg == 0) atomicAdd(KS + nh * HDD + d, ks);
}

// ---------------- out[n,l,h,e] = (Q.KV[:,e]) / (Q.Ksum + eps) ----------------
#define AT_CHUNKS 40
#define AT_RPB (LL / AT_CHUNKS)
__global__ void attn_apply_kernel(const float* __restrict__ Qb, const float* __restrict__ KV,
                                  const float* __restrict__ KS, float* __restrict__ O) {
    __shared__ float kvs[32][33];
    __shared__ float kss[32];
    int n = blockIdx.z, h = blockIdx.y;
    int nh = n * NHD + h;
    int t = threadIdx.x, lane = t & 31, w = t >> 5;
    for (int i = t; i < 1024; i += 256) kvs[i >> 5][i & 31] = KV[(size_t)nh * 1024 + i];
    if (t < 32) kss[t] = KS[nh * 32 + t];
    __syncthreads();
    int l0 = blockIdx.x * AT_RPB + w * (AT_RPB / 8);
    for (int r = 0; r < AT_RPB / 8; r++) {
        int l = l0 + r;
        size_t base = ((size_t)(n * LL + l) * NHD + h) * HDD;
        float qd = Qb[base + lane];
        float zs = qd * kss[lane];
#pragma unroll
        for (int o = 16; o; o >>= 1) zs += __shfl_xor_sync(0xffffffffu, zs, o);
        float z = 1.0f / (zs + 1e-6f);
        float acc = 0.0f;
#pragma unroll
        for (int d = 0; d < 32; d++) {
            float qv = __shfl_sync(0xffffffffu, qd, d);
            acc = fmaf(qv, kvs[d][lane], acc);
        }
        O[base + lane] = acc * z;
    }
}

// ---------------- LayerNorm over 256 (float4 path) ----------------
__global__ void layernorm_kernel(float* __restrict__ X,
                                 const float* __restrict__ g, const float* __restrict__ b) {
    int row = blockIdx.x * 8 + (threadIdx.x >> 5);
    int lane = threadIdx.x & 31;
    size_t base = (size_t)row * CD + lane * 8;
    float4 va = *(float4*)(X + base);
    float4 vb = *(float4*)(X + base + 4);
    float s = va.x + va.y + va.z + va.w + vb.x + vb.y + vb.z + vb.w;
#pragma unroll
    for (int o = 16; o; o >>= 1) s += __shfl_xor_sync(0xffffffffu, s, o);
    float mu = s * (1.0f / 256.0f);
    float qv = 0.0f;
    float vv[8] = {va.x, va.y, va.z, va.w, vb.x, vb.y, vb.z, vb.w};
#pragma unroll
    for (int i = 0; i < 8; i++) { float d = vv[i] - mu; qv = fmaf(d, d, qv); }
#pragma unroll
    for (int o = 16; o; o >>= 1) qv += __shfl_xor_sync(0xffffffffu, qv, o);
    float rs = rsqrtf(qv * (1.0f / 256.0f) + 1e-5f);
    float4 ga = *(const float4*)(g + lane * 8);
    float4 gb = *(const float4*)(g + lane * 8 + 4);
    float4 ba = *(const float4*)(b + lane * 8);
    float4 bb = *(const float4*)(b + lane * 8 + 4);
    float gg[8] = {ga.x, ga.y, ga.z, ga.w, gb.x, gb.y, gb.z, gb.w};
    float bbv[8] = {ba.x, ba.y, ba.z, ba.w, bb.x, bb.y, bb.z, bb.w};
    float out[8];
#pragma unroll
    for (int i = 0; i < 8; i++) out[i] = (vv[i] - mu) * rs * gg[i] + bbv[i];
    *(float4*)(X + base)     = make_float4(out[0], out[1], out[2], out[3]);
    *(float4*)(X + base + 4) = make_float4(out[4], out[5], out[6], out[7]);
}

// X += LayerNorm(Y)
__global__ void ln_residual_kernel(float* __restrict__ X, const float* __restrict__ Y,
                                   const float* __restrict__ g, const float* __restrict__ b) {
    int row = blockIdx.x * 8 + (threadIdx.x >> 5);
    int lane = threadIdx.x & 31;
    size_t base = (size_t)row * CD + lane * 8;
    float4 va = *(const float4*)(Y + base);
    float4 vb = *(const float4*)(Y + base + 4);
    float s = va.x + va.y + va.z + va.w + vb.x + vb.y + vb.z + vb.w;
#pragma unroll
    for (int o = 16; o; o >>= 1) s += __shfl_xor_sync(0xffffffffu, s, o);
    float mu = s * (1.0f / 256.0f);
    float qv = 0.0f;
    float vv[8] = {va.x, va.y, va.z, va.w, vb.x, vb.y, vb.z, vb.w};
#pragma unroll
    for (int i = 0; i < 8; i++) { float d = vv[i] - mu; qv = fmaf(d, d, qv); }
#pragma unroll
    for (int o = 16; o; o >>= 1) qv += __shfl_xor_sync(0xffffffffu, qv, o);
    float rs = rsqrtf(qv * (1.0f / 256.0f) + 1e-5f);
    float4 ga = *(const float4*)(g + lane * 8);
    float4 gb = *(const float4*)(g + lane * 8 + 4);
    float4 ba = *(const float4*)(b + lane * 8);
    float4 bb = *(const float4*)(b + lane * 8 + 4);
    float gg[8] = {ga.x, ga.y, ga.z, ga.w, gb.x, gb.y, gb.z, gb.w};
    float bbv[8] = {ba.x, ba.y, ba.z, ba.w, bb.x, bb.y, bb.z, bb.w};
    float4 xa = *(float4*)(X + base);
    float4 xb = *(float4*)(X + base + 4);
    float xx[8] = {xa.x, xa.y, xa.z, xa.w, xb.x, xb.y, xb.z, xb.w};
#pragma unroll
    for (int i = 0; i < 8; i++) xx[i] += (vv[i] - mu) * rs * gg[i] + bbv[i];
    *(float4*)(X + base)     = make_float4(xx[0], xx[1], xx[2], xx[3]);
    *(float4*)(X + base + 4) = make_float4(xx[4], xx[5], xx[6], xx[7]);
}

// ---------------- launch ----------------
extern "C" void kernel_launch(void* const* d_in, const int* in_sizes, int n_in,
                              void* d_out, int out_size) {
    const float* feat0 = (const float*)d_in[0];
    const float* feat1 = (const float*)d_in[1];
    const float* Wq = (const float*)d_in[2];
    const float* Wk = (const float*)d_in[3];
    const float* Wv = (const float*)d_in[4];
    const float* Wm = (const float*)d_in[5];
    const float* W1 = (const float*)d_in[6];
    const float* W2 = (const float*)d_in[7];
    const float* g1 = (const float*)d_in[8];
    const float* b1 = (const float*)d_in[9];
    const float* g2 = (const float*)d_in[10];
    const float* b2 = (const float*)d_in[11];

    float *F0, *F1, *Qb, *Kb, *Vb, *KV, *KS, *PE;
    float *wQ, *wK, *wV, *wM, *w1p, *w2p;
    cudaGetSymbolAddress((void**)&F0,  g_F0);
    cudaGetSymbolAddress((void**)&F1,  g_F1);
    cudaGetSymbolAddress((void**)&Qb,  g_Q);
    cudaGetSymbolAddress((void**)&Kb,  g_K);
    cudaGetSymbolAddress((void**)&Vb,  g_V);
    cudaGetSymbolAddress((void**)&KV,  g_KV);
    cudaGetSymbolAddress((void**)&KS,  g_KS);
    cudaGetSymbolAddress((void**)&PE,  g_PE);
    cudaGetSymbolAddress((void**)&wQ,  g_Wq);
    cudaGetSymbolAddress((void**)&wK,  g_Wk);
    cudaGetSymbolAddress((void**)&wV,  g_Wv);
    cudaGetSymbolAddress((void**)&wM,  g_Wm);
    cudaGetSymbolAddress((void**)&w1p, g_W1);
    cudaGetSymbolAddress((void**)&w2p, g_W2);

    cudaFuncSetAttribute(tgemm_kernel,
                         cudaFuncAttributeMaxDynamicSharedMemorySize, SMEM_BYTES);

    weight_prep_kernel<<<(2 * 2 * CD * CD + 255) / 256, 256>>>(Wq, Wk, Wv, Wm, W1, W2);
    pe_precompute_kernel<<<(CD * LL + 255) / 256, 256>>>(PE);

    dim3 tb(32, 8);
    dim3 tg(LL / 32, CD / 32, NB);
    build_pe_kernel<<<tg, tb>>>(feat0, PE, F0);
    build_pe_kernel<<<tg, tb>>>(feat1, PE, F1);

    dim3 gg(CD / 128, MR / 128);

    for (int i = 0; i < 2; i++) {
        const float* wq = wQ + (size_t)i * CD * CD;
        const float* wk = wK + (size_t)i * CD * CD;
        const float* wv = wV + (size_t)i * CD * CD;
        const float* wm = wM + (size_t)i * CD * CD;
        const float* w1 = w1p + (size_t)i * 2 * CD * CD;
        const float* w2 = w2p + (size_t)i * CD * CD;

        tgemm_kernel<<<gg, 256, SMEM_BYTES>>>(F0, F0, wq, Qb, MR, CD, CD, CD, EPI_ELU1);
        tgemm_kernel<<<gg, 256, SMEM_BYTES>>>(F1, F1, wk, Kb, MR, CD, CD, CD, EPI_ELU1);
        tgemm_kernel<<<gg, 256, SMEM_BYTES>>>(F1, F1, wv, Vb, MR, CD, CD, CD, EPI_NONE);

        cudaMemsetAsync(KV, 0, sizeof(float) * NB * NHD * HDD * HDD, 0);
        cudaMemsetAsync(KS, 0, sizeof(float) * NB * NHD * HDD, 0);
        kv_reduce_kernel<<<dim3(NB * NHD, KV_CHUNKS), 256>>>(Kb, Vb, KV, KS);

        attn_apply_kernel<<<dim3(AT_CHUNKS, NHD, NB), 256>>>(Qb, KV, KS, Kb);

        tgemm_kernel<<<gg, 256, SMEM_BYTES>>>(Kb, Kb, wm, Vb, MR, CD, CD, CD, EPI_NONE);
        layernorm_kernel<<<MR / 8, 256>>>(Vb, g1 + i * CD, b1 + i * CD);

        tgemm_kernel<<<gg, 256, SMEM_BYTES>>>(F0, Vb, w1, Qb, MR, 2 * CD, CD, CD, EPI_RELU);
        tgemm_kernel<<<gg, 256, SMEM_BYTES>>>(Qb, Qb, w2, Kb, MR, CD, CD, CD, EPI_NONE);
        ln_residual_kernel<<<MR / 8, 256>>>(F0, Kb, g2 + i * CD, b2 + i * CD);
    }

    unbuild_kernel<<<tg, tb>>>(F0, (float*)d_out);
}

// round 8
// speedup vs baseline: 1.9124x; 1.9124x over previous
#include <cuda_runtime.h>
#include <cuda_fp16.h>
#include <cstdint>

// Problem constants
#define NB    16
#define CD    256
#define HH    80
#define WW    60
#define LL    4800            // HH*WW
#define NHD   8
#define HDD   32
#define MR    (NB*LL)         // 76800 rows

#define EPI_NONE 0
#define EPI_ELU1 1
#define EPI_RELU 2

// ---------------- scratch (static device globals; no allocation) ----------------
__device__ float  g_F0 [(size_t)MR * CD];    // exact x (residual/output)
__device__ float  g_Vf [(size_t)MR * CD];    // f32 GEMM outputs (merge / ffn2)
__device__ float  g_Kf [(size_t)MR * CD];
__device__ __half g_F0h[(size_t)MR * CD];
__device__ __half g_F1h[(size_t)MR * CD];
__device__ __half g_Qh [(size_t)MR * CD];
__device__ __half g_Kh [(size_t)MR * CD];
__device__ __half g_Vh [(size_t)MR * CD];
__device__ float  g_PE [(size_t)CD * LL];
__device__ float  g_KV [NB * NHD * HDD * HDD];
__device__ float  g_KS [NB * NHD * HDD];
// fp16 weights, k-pair interleaved: WH[((k>>1)*N + n)*2 + (k&1)] = W[k][n]
__device__ __half g_WqH[2 * CD * CD];
__device__ __half g_WkH[2 * CD * CD];
__device__ __half g_WvH[2 * CD * CD];
__device__ __half g_WmH[2 * CD * CD];
__device__ __half g_W1H[2 * 2 * CD * CD];
__device__ __half g_W2H[2 * CD * CD];

// ---------------- weight prep: fp16 + interleave ----------------
__global__ void weight_prep_kernel(
    const float* __restrict__ wq, const float* __restrict__ wk,
    const float* __restrict__ wv, const float* __restrict__ wm,
    const float* __restrict__ w1, const float* __restrict__ w2)
{
    int i = blockIdx.x * blockDim.x + threadIdx.x;
    const int S = 2 * CD * CD;              // 131072
    if (i < S) {
        int li = i >> 16;                   // CD*CD = 65536
        int r  = i & 65535;
        int k = r >> 8, n = r & 255;
        int dst = li * 65536 + (((k >> 1) << 8) + n) * 2 + (k & 1);
        g_WqH[dst] = __float2half_rn(wq[i]);
        g_WkH[dst] = __float2half_rn(wk[i]);
        g_WvH[dst] = __float2half_rn(wv[i]);
        g_WmH[dst] = __float2half_rn(wm[i]);
        g_W2H[dst] = __float2half_rn(w2[i]);
    }
    if (i < 2 * S) {                        // W1: [512][256] per layer
        int li = i >> 17;                   // 131072 per layer
        int r  = i & 131071;
        int k = r >> 8, n = r & 255;
        int dst = li * 131072 + (((k >> 1) << 8) + n) * 2 + (k & 1);
        g_W1H[dst] = __float2half_rn(w1[i]);
    }
}

// ---------------- positional encoding ----------------
// fac = (-log(1e4)/256)//2 == -1.0  =>  div[j] = exp(-2*j)
__global__ void pe_precompute_kernel(float* __restrict__ PE) {
    int idx = blockIdx.x * blockDim.x + threadIdx.x;
    if (idx >= CD * LL) return;
    int c = idx / LL, l = idx % LL;
    int j = c >> 2, r = c & 3;
    int h = l / WW, w = l % WW;
    float f = expf(-2.0f * (float)j);
    float pos = (r < 2) ? (float)(w + 1) : (float)(h + 1);
    float arg = pos * f;
    PE[idx] = (r & 1) ? cosf(arg) : sinf(arg);
}

// NCHW -> [N,L,C] with PE; writes optional f32 + fp16
__global__ void build_pe_kernel(const float* __restrict__ feat, const float* __restrict__ PE,
                                float* __restrict__ outF, __half* __restrict__ outH) {
    __shared__ float tile[32][33];
    int n  = blockIdx.z;
    int c0 = blockIdx.y * 32;
    int l0 = blockIdx.x * 32;
    int tx = threadIdx.x, ty = threadIdx.y;
#pragma unroll
    for (int i = 0; i < 4; i++) {
        int c = c0 + ty + i * 8;
        int l = l0 + tx;
        tile[ty + i * 8][tx] = feat[((size_t)n * CD + c) * LL + l] + PE[(size_t)c * LL + l];
    }
    __syncthreads();
#pragma unroll
    for (int i = 0; i < 4; i++) {
        int l = l0 + ty + i * 8;
        int c = c0 + tx;
        float v = tile[tx][ty + i * 8];
        size_t o = ((size_t)n * LL + l) * CD + c;
        if (outF) outF[o] = v;
        outH[o] = __float2half_rn(v);
    }
}

__global__ void unbuild_kernel(const float* __restrict__ in, float* __restrict__ out) {
    __shared__ float tile[32][33];
    int n  = blockIdx.z;
    int c0 = blockIdx.y * 32;
    int l0 = blockIdx.x * 32;
    int tx = threadIdx.x, ty = threadIdx.y;
#pragma unroll
    for (int i = 0; i < 4; i++) {
        int l = l0 + ty + i * 8;
        int c = c0 + tx;
        tile[ty + i * 8][tx] = in[((size_t)n * LL + l) * CD + c];
    }
    __syncthreads();
#pragma unroll
    for (int i = 0; i < 4; i++) {
        int c = c0 + ty + i * 8;
        int l = l0 + tx;
        out[((size_t)n * CD + c) * LL + l] = tile[tx][ty + i * 8];
    }
}

// ---------------- FP16 tensor-core GEMM (m16n8k16, f32 accum) ----------------
// C[M,N] = epi( [A|A2][M,Ktot] @ B ), A row-major fp16; B fp16 k-pair interleaved
// ([K/2][N] 32-bit words, each = halves k_even,k_odd of column n).
// BM=BN=128, BK=16, 8 warps, warp tile 32x64. Double-buffered cp.async (R3 schedule).
#define ASW 12                 // A row stride in 32-bit words (16 halves + pad)
#define BSW 136                // B k-pair row stride in words (128 + pad)
#define AS_WORDS (128 * ASW)
#define BS_WORDS (8 * BSW)

__device__ __forceinline__ void cp16(void* dst, const void* src) {
    uint32_t d = (uint32_t)__cvta_generic_to_shared(dst);
    asm volatile("cp.async.cg.shared.global [%0], [%1], 16;\n" :: "r"(d), "l"(src));
}

__global__ __launch_bounds__(256, 2) void hgemm_kernel(
    const __half* __restrict__ A, const __half* __restrict__ A2,
    const __half* __restrict__ B, void* __restrict__ Cout,
    int M, int Ktot, int K1, int N, int epi, int outHalf)
{
    __shared__ uint32_t As2[2][AS_WORDS];
    __shared__ uint32_t Bs2[2][BS_WORDS];

    int tid = threadIdx.x;
    int warp = tid >> 5;
    int lane = tid & 31;
    int g = lane >> 2;
    int q = lane & 3;
    int rowBase = blockIdx.y * 128;
    int colBase = blockIdx.x * 128;
    int wm0 = (warp >> 1) * 32;
    int wn0 = (warp & 1) * 64;
    int K2 = Ktot - K1;
    int NS = Ktot >> 4;

    float acc[2][8][4];
#pragma unroll
    for (int mt = 0; mt < 2; mt++)
#pragma unroll
        for (int nt = 0; nt < 8; nt++)
#pragma unroll
            for (int r = 0; r < 4; r++) acc[mt][nt][r] = 0.0f;

    // A: 256 chunks of 16B (8 halves): row = tid>>1, j = tid&1 (k-halves j*8..j*8+7)
    int aRow = tid >> 1, aJ = tid & 1;
    // B: 256 chunks: k-pair row = tid>>5 (0..7), word col = (tid&31)*4
    int bKp = tid >> 5, bN0 = (tid & 31) << 2;

    auto issue = [&](int s, int buf) {
        int k0 = s << 4;
        int kk = k0 + aJ * 8;
        const __half* srcA = (kk < K1)
            ? (A  + (size_t)(rowBase + aRow) * K1 + kk)
            : (A2 + (size_t)(rowBase + aRow) * K2 + (kk - K1));
        cp16(&As2[buf][aRow * ASW + aJ * 4], srcA);
        const uint32_t* Bw = (const uint32_t*)B;
        cp16(&Bs2[buf][bKp * BSW + bN0],
             Bw + (size_t)(s * 8 + bKp) * N + colBase + bN0);
    };

    issue(0, 0);
    asm volatile("cp.async.commit_group;\n");

    int buf = 0;
    for (int s = 0; s < NS; s++) {
        if (s + 1 < NS) {
            issue(s + 1, buf ^ 1);
            asm volatile("cp.async.commit_group;\n");
            asm volatile("cp.async.wait_group 1;\n");
        } else {
            asm volatile("cp.async.wait_group 0;\n");
        }
        __syncthreads();

        const uint32_t* AsB = As2[buf];
        const uint32_t* BsB = Bs2[buf];
        uint32_t af[2][4];
#pragma unroll
        for (int mt = 0; mt < 2; mt++) {
            int m = wm0 + mt * 16;
            af[mt][0] = AsB[(m + g    ) * ASW + q    ];
            af[mt][1] = AsB[(m + g + 8) * ASW + q    ];
            af[mt][2] = AsB[(m + g    ) * ASW + q + 4];
            af[mt][3] = AsB[(m + g + 8) * ASW + q + 4];
        }
        uint32_t bf[8][2];
#pragma unroll
        for (int nt = 0; nt < 8; nt++) {
            int n = wn0 + nt * 8 + g;
            bf[nt][0] = BsB[q       * BSW + n];
            bf[nt][1] = BsB[(q + 4) * BSW + n];
        }
#pragma unroll
        for (int mt = 0; mt < 2; mt++)
#pragma unroll
            for (int nt = 0; nt < 8; nt++) {
                asm volatile(
                    "mma.sync.aligned.m16n8k16.row.col.f32.f16.f16.f32 "
                    "{%0,%1,%2,%3}, {%4,%5,%6,%7}, {%8,%9}, {%0,%1,%2,%3};\n"
                    : "+f"(acc[mt][nt][0]), "+f"(acc[mt][nt][1]),
                      "+f"(acc[mt][nt][2]), "+f"(acc[mt][nt][3])
                    : "r"(af[mt][0]), "r"(af[mt][1]), "r"(af[mt][2]), "r"(af[mt][3]),
                      "r"(bf[nt][0]), "r"(bf[nt][1]));
            }
        buf ^= 1;
        __syncthreads();
    }

    // epilogue: c0,c1 -> (row g, col 2q..2q+1), c2,c3 -> (row g+8, same cols)
#pragma unroll
    for (int mt = 0; mt < 2; mt++) {
        int row = rowBase + wm0 + mt * 16 + g;
#pragma unroll
        for (int nt = 0; nt < 8; nt++) {
            int col = colBase + wn0 + nt * 8 + 2 * q;
            float v0 = acc[mt][nt][0], v1 = acc[mt][nt][1];
            float v2 = acc[mt][nt][2], v3 = acc[mt][nt][3];
            if (epi == EPI_ELU1) {
                v0 = (v0 > 0.f) ? v0 + 1.f : expf(v0);
                v1 = (v1 > 0.f) ? v1 + 1.f : expf(v1);
                v2 = (v2 > 0.f) ? v2 + 1.f : expf(v2);
                v3 = (v3 > 0.f) ? v3 + 1.f : expf(v3);
            } else if (epi == EPI_RELU) {
                v0 = fmaxf(v0, 0.f); v1 = fmaxf(v1, 0.f);
                v2 = fmaxf(v2, 0.f); v3 = fmaxf(v3, 0.f);
            }
            if (outHalf) {
                __half* Ch = (__half*)Cout;
                *(__half2*)(Ch + (size_t)row * N + col)       = __floats2half2_rn(v0, v1);
                *(__half2*)(Ch + (size_t)(row + 8) * N + col) = __floats2half2_rn(v2, v3);
            } else {
                float* Cf = (float*)Cout;
                *(float2*)(Cf + (size_t)row * N + col)       = make_float2(v0, v1);
                *(float2*)(Cf + (size_t)(row + 8) * N + col) = make_float2(v2, v3);
            }
        }
    }
}

// ---------------- KV = sum_s K[s,d]*v[s,e], Ksum per (n,h), fp16 inputs ----------------
#define KV_CHUNKS 20
#define KV_SC (LL / KV_CHUNKS)
__global__ void kv_reduce_kernel(const __half* __restrict__ Kb, const __half* __restrict__ Vb,
                                 float* __restrict__ KV, float* __restrict__ KS) {
    int nh = blockIdx.x;
    int n = nh >> 3, h = nh & 7;
    int t = threadIdx.x;
    int d = t & 31;
    int eg = t >> 5;
    int s0 = blockIdx.y * KV_SC;
    float a0 = 0, a1 = 0, a2 = 0, a3 = 0, ks = 0;
    for (int s = s0; s < s0 + KV_SC; s++) {
        size_t base = ((size_t)(n * LL + s) * NHD + h) * HDD;
        float kd = __half2float(Kb[base + d]);
        const __half2* vp = (const __half2*)(Vb + base + eg * 4);
        float2 f0 = __half22float2(vp[0]);
        float2 f1 = __half22float2(vp[1]);
        a0 = fmaf(kd, f0.x, a0);
        a1 = fmaf(kd, f0.y, a1);
        a2 = fmaf(kd, f1.x, a2);
        a3 = fmaf(kd, f1.y, a3);
        ks += kd;
    }
    float* kvp = KV + ((size_t)nh * HDD + d) * HDD + eg * 4;
    atomicAdd(kvp + 0, a0);
    atomicAdd(kvp + 1, a1);
    atomicAdd(kvp + 2, a2);
    atomicAdd(kvp + 3, a3);
    if (eg == 0) atomicAdd(KS + nh * HDD + d, ks);
}

// ---------------- out = (Q.KV[:,e]) / (Q.Ksum + eps); fp16 in/out (in-place ok) ----------------
#define AT_CHUNKS 40
#define AT_RPB (LL / AT_CHUNKS)
__global__ void attn_apply_kernel(__half* __restrict__ Qb, const float* __restrict__ KV,
                                  const float* __restrict__ KS) {
    __shared__ float kvs[32][33];
    __shared__ float kss[32];
    int n = blockIdx.z, h = blockIdx.y;
    int nh = n * NHD + h;
    int t = threadIdx.x, lane = t & 31, w = t >> 5;
    for (int i = t; i < 1024; i += 256) kvs[i >> 5][i & 31] = KV[(size_t)nh * 1024 + i];
    if (t < 32) kss[t] = KS[nh * 32 + t];
    __syncthreads();
    int l0 = blockIdx.x * AT_RPB + w * (AT_RPB / 8);
    for (int r = 0; r < AT_RPB / 8; r++) {
        int l = l0 + r;
        size_t base = ((size_t)(n * LL + l) * NHD + h) * HDD;
        float qd = __half2float(Qb[base + lane]);
        float zs = qd * kss[lane];
#pragma unroll
        for (int o = 16; o; o >>= 1) zs += __shfl_xor_sync(0xffffffffu, zs, o);
        float z = 1.0f / (zs + 1e-6f);
        float acc = 0.0f;
#pragma unroll
        for (int d = 0; d < 32; d++) {
            float qv = __shfl_sync(0xffffffffu, qd, d);
            acc = fmaf(qv, kvs[d][lane], acc);
        }
        Qb[base + lane] = __float2half_rn(acc * z);
    }
}

// ---------------- LayerNorm over 256: f32 in -> fp16 out ----------------
__global__ void layernorm_h_kernel(const float* __restrict__ X, __half* __restrict__ XH,
                                   const float* __restrict__ g, const float* __restrict__ b) {
    int row = blockIdx.x * 8 + (threadIdx.x >> 5);
    int lane = threadIdx.x & 31;
    size_t base = (size_t)row * CD;
    float v[8];
    float s = 0.0f;
#pragma unroll
    for (int i = 0; i < 8; i++) { v[i] = X[base + i * 32 + lane]; s += v[i]; }
#pragma unroll
    for (int o = 16; o; o >>= 1) s += __shfl_xor_sync(0xffffffffu, s, o);
    float mu = s * (1.0f / 256.0f);
    float qv = 0.0f;
#pragma unroll
    for (int i = 0; i < 8; i++) { float d = v[i] - mu; qv = fmaf(d, d, qv); }
#pragma unroll
    for (int o = 16; o; o >>= 1) qv += __shfl_xor_sync(0xffffffffu, qv, o);
    float rs = rsqrtf(qv * (1.0f / 256.0f) + 1e-5f);
#pragma unroll
    for (int i = 0; i < 8; i++)
        XH[base + i * 32 + lane] =
            __float2half_rn((v[i] - mu) * rs * g[i * 32 + lane] + b[i * 32 + lane]);
}

// X(f32) += LayerNorm(Y f32); XH = fp16(X)
__global__ void ln_residual_kernel(float* __restrict__ X, __half* __restrict__ XH,
                                   const float* __restrict__ Y,
                                   const float* __restrict__ g, const float* __restrict__ b) {
    int row = blockIdx.x * 8 + (threadIdx.x >> 5);
    int lane = threadIdx.x & 31;
    size_t base = (size_t)row * CD;
    float v[8];
    float s = 0.0f;
#pragma unroll
    for (int i = 0; i < 8; i++) { v[i] = Y[base + i * 32 + lane]; s += v[i]; }
#pragma unroll
    for (int o = 16; o; o >>= 1) s += __shfl_xor_sync(0xffffffffu, s, o);
    float mu = s * (1.0f / 256.0f);
    float qv = 0.0f;
#pragma unroll
    for (int i = 0; i < 8; i++) { float d = v[i] - mu; qv = fmaf(d, d, qv); }
#pragma unroll
    for (int o = 16; o; o >>= 1) qv += __shfl_xor_sync(0xffffffffu, qv, o);
    float rs = rsqrtf(qv * (1.0f / 256.0f) + 1e-5f);
#pragma unroll
    for (int i = 0; i < 8; i++) {
        size_t o = base + i * 32 + lane;
        float nx = X[o] + (v[i] - mu) * rs * g[i * 32 + lane] + b[i * 32 + lane];
        X[o] = nx;
        XH[o] = __float2half_rn(nx);
    }
}

// ---------------- launch ----------------
extern "C" void kernel_launch(void* const* d_in, const int* in_sizes, int n_in,
                              void* d_out, int out_size) {
    const float* feat0 = (const float*)d_in[0];
    const float* feat1 = (const float*)d_in[1];
    const float* Wq = (const float*)d_in[2];
    const float* Wk = (const float*)d_in[3];
    const float* Wv = (const float*)d_in[4];
    const float* Wm = (const float*)d_in[5];
    const float* W1 = (const float*)d_in[6];
    const float* W2 = (const float*)d_in[7];
    const float* g1 = (const float*)d_in[8];
    const float* b1 = (const float*)d_in[9];
    const float* g2 = (const float*)d_in[10];
    const float* b2 = (const float*)d_in[11];

    float *F0, *Vf, *Kf, *KV, *KS, *PE;
    __half *F0h, *F1h, *Qh, *Kh, *Vh;
    __half *wQ, *wK, *wV, *wM, *w1p, *w2p;
    cudaGetSymbolAddress((void**)&F0,  g_F0);
    cudaGetSymbolAddress((void**)&Vf,  g_Vf);
    cudaGetSymbolAddress((void**)&Kf,  g_Kf);
    cudaGetSymbolAddress((void**)&KV,  g_KV);
    cudaGetSymbolAddress((void**)&KS,  g_KS);
    cudaGetSymbolAddress((void**)&PE,  g_PE);
    cudaGetSymbolAddress((void**)&F0h, g_F0h);
    cudaGetSymbolAddress((void**)&F1h, g_F1h);
    cudaGetSymbolAddress((void**)&Qh,  g_Qh);
    cudaGetSymbolAddress((void**)&Kh,  g_Kh);
    cudaGetSymbolAddress((void**)&Vh,  g_Vh);
    cudaGetSymbolAddress((void**)&wQ,  g_WqH);
    cudaGetSymbolAddress((void**)&wK,  g_WkH);
    cudaGetSymbolAddress((void**)&wV,  g_WvH);
    cudaGetSymbolAddress((void**)&wM,  g_WmH);
    cudaGetSymbolAddress((void**)&w1p, g_W1H);
    cudaGetSymbolAddress((void**)&w2p, g_W2H);

    weight_prep_kernel<<<(2 * 2 * CD * CD + 255) / 256, 256>>>(Wq, Wk, Wv, Wm, W1, W2);
    pe_precompute_kernel<<<(CD * LL + 255) / 256, 256>>>(PE);

    dim3 tb(32, 8);
    dim3 tg(LL / 32, CD / 32, NB);
    build_pe_kernel<<<tg, tb>>>(feat0, PE, F0, F0h);
    build_pe_kernel<<<tg, tb>>>(feat1, PE, nullptr, F1h);

    dim3 gg(CD / 128, MR / 128);

    for (int i = 0; i < 2; i++) {
        const __half* wq = wQ + (size_t)i * CD * CD;
        const __half* wk = wK + (size_t)i * CD * CD;
        const __half* wv = wV + (size_t)i * CD * CD;
        const __half* wm = wM + (size_t)i * CD * CD;
        const __half* w1 = w1p + (size_t)i * 2 * CD * CD;
        const __half* w2 = w2p + (size_t)i * CD * CD;

        // projections (fp16 out): q -> Qh, k -> Kh, v -> Vh
        hgemm_kernel<<<gg, 256>>>(F0h, F0h, wq, Qh, MR, CD, CD, CD, EPI_ELU1, 1);
        hgemm_kernel<<<gg, 256>>>(F1h, F1h, wk, Kh, MR, CD, CD, CD, EPI_ELU1, 1);
        hgemm_kernel<<<gg, 256>>>(F1h, F1h, wv, Vh, MR, CD, CD, CD, EPI_NONE, 1);

        cudaMemsetAsync(KV, 0, sizeof(float) * NB * NHD * HDD * HDD, 0);
        cudaMemsetAsync(KS, 0, sizeof(float) * NB * NHD * HDD, 0);
        kv_reduce_kernel<<<dim3(NB * NHD, KV_CHUNKS), 256>>>(Kh, Vh, KV, KS);

        // attention apply in place on Qh
        attn_apply_kernel<<<dim3(AT_CHUNKS, NHD, NB), 256>>>(Qh, KV, KS);

        // merge: f32 out -> Vf; LN1 -> Vh (fp16)
        hgemm_kernel<<<gg, 256>>>(Qh, Qh, wm, Vf, MR, CD, CD, CD, EPI_NONE, 0);
        layernorm_h_kernel<<<MR / 8, 256>>>(Vf, Vh, g1 + i * CD, b1 + i * CD);

        // FFN1: [F0h|Vh] @ W1, relu, fp16 -> Kh ; FFN2: f32 -> Kf ; residual+LN2
        hgemm_kernel<<<gg, 256>>>(F0h, Vh, w1, Kh, MR, 2 * CD, CD, CD, EPI_RELU, 1);
        hgemm_kernel<<<gg, 256>>>(Kh, Kh, w2, Kf, MR, CD, CD, CD, EPI_NONE, 0);
        ln_residual_kernel<<<MR / 8, 256>>>(F0, F0h, Kf, g2 + i * CD, b2 + i * CD);
    }

    unbuild_kernel<<<tg, tb>>>(F0, (float*)d_out);
}

// round 9
// speedup vs baseline: 1.9702x; 1.0302x over previous
#include <cuda_runtime.h>
#include <cuda_fp16.h>
#include <cstdint>

// Problem constants
#define NB    16
#define CD    256
#define HH    80
#define WW    60
#define LL    4800            // HH*WW
#define NHD   8
#define HDD   32
#define MR    (NB*LL)         // 76800 rows

#define EPI_NONE 0
#define EPI_ELU1 1
#define EPI_RELU 2

// ---------------- scratch (static device globals; no allocation) ----------------
__device__ float  g_F0 [(size_t)MR * CD];    // exact x (residual/output)
__device__ __half g_F0h[(size_t)MR * CD];
__device__ __half g_F1h[(size_t)MR * CD];
__device__ __half g_Qh [(size_t)MR * CD];
__device__ __half g_Kh [(size_t)MR * CD];
__device__ __half g_Vh [(size_t)MR * CD];
__device__ float  g_PE [(size_t)CD * LL];
__device__ float  g_KV [NB * NHD * HDD * HDD];
__device__ float  g_KS [NB * NHD * HDD];
// fp16 weights, k-pair interleaved: WH[((k>>1)*N + n)*2 + (k&1)] = W[k][n]
__device__ __half g_WqH[2 * CD * CD];
__device__ __half g_WkH[2 * CD * CD];
__device__ __half g_WvH[2 * CD * CD];
__device__ __half g_WmH[2 * CD * CD];
__device__ __half g_W1H[2 * 2 * CD * CD];
__device__ __half g_W2H[2 * CD * CD];

// ---------------- weight prep: fp16 + interleave ----------------
__global__ void weight_prep_kernel(
    const float* __restrict__ wq, const float* __restrict__ wk,
    const float* __restrict__ wv, const float* __restrict__ wm,
    const float* __restrict__ w1, const float* __restrict__ w2)
{
    int i = blockIdx.x * blockDim.x + threadIdx.x;
    const int S = 2 * CD * CD;              // 131072
    if (i < S) {
        int li = i >> 16;                   // CD*CD = 65536
        int r  = i & 65535;
        int k = r >> 8, n = r & 255;
        int dst = li * 65536 + (((k >> 1) << 8) + n) * 2 + (k & 1);
        g_WqH[dst] = __float2half_rn(wq[i]);
        g_WkH[dst] = __float2half_rn(wk[i]);
        g_WvH[dst] = __float2half_rn(wv[i]);
        g_WmH[dst] = __float2half_rn(wm[i]);
        g_W2H[dst] = __float2half_rn(w2[i]);
    }
    if (i < 2 * S) {                        // W1: [512][256] per layer
        int li = i >> 17;                   // 131072 per layer
        int r  = i & 131071;
        int k = r >> 8, n = r & 255;
        int dst = li * 131072 + (((k >> 1) << 8) + n) * 2 + (k & 1);
        g_W1H[dst] = __float2half_rn(w1[i]);
    }
}

// ---------------- positional encoding ----------------
// fac = (-log(1e4)/256)//2 == -1.0  =>  div[j] = exp(-2*j)
__global__ void pe_precompute_kernel(float* __restrict__ PE) {
    int idx = blockIdx.x * blockDim.x + threadIdx.x;
    if (idx >= CD * LL) return;
    int c = idx / LL, l = idx % LL;
    int j = c >> 2, r = c & 3;
    int h = l / WW, w = l % WW;
    float f = expf(-2.0f * (float)j);
    float pos = (r < 2) ? (float)(w + 1) : (float)(h + 1);
    float arg = pos * f;
    PE[idx] = (r & 1) ? cosf(arg) : sinf(arg);
}

// NCHW -> [N,L,C] with PE; writes optional f32 + fp16
__global__ void build_pe_kernel(const float* __restrict__ feat, const float* __restrict__ PE,
                                float* __restrict__ outF, __half* __restrict__ outH) {
    __shared__ float tile[32][33];
    int n  = blockIdx.z;
    int c0 = blockIdx.y * 32;
    int l0 = blockIdx.x * 32;
    int tx = threadIdx.x, ty = threadIdx.y;
#pragma unroll
    for (int i = 0; i < 4; i++) {
        int c = c0 + ty + i * 8;
        int l = l0 + tx;
        tile[ty + i * 8][tx] = feat[((size_t)n * CD + c) * LL + l] + PE[(size_t)c * LL + l];
    }
    __syncthreads();
#pragma unroll
    for (int i = 0; i < 4; i++) {
        int l = l0 + ty + i * 8;
        int c = c0 + tx;
        float v = tile[tx][ty + i * 8];
        size_t o = ((size_t)n * LL + l) * CD + c;
        if (outF) outF[o] = v;
        outH[o] = __float2half_rn(v);
    }
}

__global__ void unbuild_kernel(const float* __restrict__ in, float* __restrict__ out) {
    __shared__ float tile[32][33];
    int n  = blockIdx.z;
    int c0 = blockIdx.y * 32;
    int l0 = blockIdx.x * 32;
    int tx = threadIdx.x, ty = threadIdx.y;
#pragma unroll
    for (int i = 0; i < 4; i++) {
        int l = l0 + ty + i * 8;
        int c = c0 + tx;
        tile[ty + i * 8][tx] = in[((size_t)n * LL + l) * CD + c];
    }
    __syncthreads();
#pragma unroll
    for (int i = 0; i < 4; i++) {
        int c = c0 + ty + i * 8;
        int l = l0 + tx;
        out[((size_t)n * CD + c) * LL + l] = tile[tx][ty + i * 8];
    }
}

// ---------------- FP16 tensor-core GEMM (m16n8k16, f32 accum) ----------------
#define ASW 12                 // A row stride in 32-bit words (16 halves + pad)
#define BSW 136                // B k-pair row stride in words (128 + pad)
#define AS_WORDS (128 * ASW)
#define BS_WORDS (8 * BSW)

__device__ __forceinline__ void cp16(void* dst, const void* src) {
    uint32_t d = (uint32_t)__cvta_generic_to_shared(dst);
    asm volatile("cp.async.cg.shared.global [%0], [%1], 16;\n" :: "r"(d), "l"(src));
}

__global__ __launch_bounds__(256, 2) void hgemm_kernel(
    const __half* __restrict__ A, const __half* __restrict__ A2,
    const __half* __restrict__ B, void* __restrict__ Cout,
    int M, int Ktot, int K1, int N, int epi, int outHalf)
{
    __shared__ uint32_t As2[2][AS_WORDS];
    __shared__ uint32_t Bs2[2][BS_WORDS];

    int tid = threadIdx.x;
    int warp = tid >> 5;
    int lane = tid & 31;
    int g = lane >> 2;
    int q = lane & 3;
    int rowBase = blockIdx.y * 128;
    int colBase = blockIdx.x * 128;
    int wm0 = (warp >> 1) * 32;
    int wn0 = (warp & 1) * 64;
    int K2 = Ktot - K1;
    int NS = Ktot >> 4;

    float acc[2][8][4];
#pragma unroll
    for (int mt = 0; mt < 2; mt++)
#pragma unroll
        for (int nt = 0; nt < 8; nt++)
#pragma unroll
            for (int r = 0; r < 4; r++) acc[mt][nt][r] = 0.0f;

    int aRow = tid >> 1, aJ = tid & 1;
    int bKp = tid >> 5, bN0 = (tid & 31) << 2;

    auto issue = [&](int s, int buf) {
        int k0 = s << 4;
        int kk = k0 + aJ * 8;
        const __half* srcA = (kk < K1)
            ? (A  + (size_t)(rowBase + aRow) * K1 + kk)
            : (A2 + (size_t)(rowBase + aRow) * K2 + (kk - K1));
        cp16(&As2[buf][aRow * ASW + aJ * 4], srcA);
        const uint32_t* Bw = (const uint32_t*)B;
        cp16(&Bs2[buf][bKp * BSW + bN0],
             Bw + (size_t)(s * 8 + bKp) * N + colBase + bN0);
    };

    issue(0, 0);
    asm volatile("cp.async.commit_group;\n");

    int buf = 0;
    for (int s = 0; s < NS; s++) {
        if (s + 1 < NS) {
            issue(s + 1, buf ^ 1);
            asm volatile("cp.async.commit_group;\n");
            asm volatile("cp.async.wait_group 1;\n");
        } else {
            asm volatile("cp.async.wait_group 0;\n");
        }
        __syncthreads();

        const uint32_t* AsB = As2[buf];
        const uint32_t* BsB = Bs2[buf];
        uint32_t af[2][4];
#pragma unroll
        for (int mt = 0; mt < 2; mt++) {
            int m = wm0 + mt * 16;
            af[mt][0] = AsB[(m + g    ) * ASW + q    ];
            af[mt][1] = AsB[(m + g + 8) * ASW + q    ];
            af[mt][2] = AsB[(m + g    ) * ASW + q + 4];
            af[mt][3] = AsB[(m + g + 8) * ASW + q + 4];
        }
        uint32_t bf[8][2];
#pragma unroll
        for (int nt = 0; nt < 8; nt++) {
            int n = wn0 + nt * 8 + g;
            bf[nt][0] = BsB[q       * BSW + n];
            bf[nt][1] = BsB[(q + 4) * BSW + n];
        }
#pragma unroll
        for (int mt = 0; mt < 2; mt++)
#pragma unroll
            for (int nt = 0; nt < 8; nt++) {
                asm volatile(
                    "mma.sync.aligned.m16n8k16.row.col.f32.f16.f16.f32 "
                    "{%0,%1,%2,%3}, {%4,%5,%6,%7}, {%8,%9}, {%0,%1,%2,%3};\n"
                    : "+f"(acc[mt][nt][0]), "+f"(acc[mt][nt][1]),
                      "+f"(acc[mt][nt][2]), "+f"(acc[mt][nt][3])
                    : "r"(af[mt][0]), "r"(af[mt][1]), "r"(af[mt][2]), "r"(af[mt][3]),
                      "r"(bf[nt][0]), "r"(bf[nt][1]));
            }
        buf ^= 1;
        __syncthreads();
    }

#pragma unroll
    for (int mt = 0; mt < 2; mt++) {
        int row = rowBase + wm0 + mt * 16 + g;
#pragma unroll
        for (int nt = 0; nt < 8; nt++) {
            int col = colBase + wn0 + nt * 8 + 2 * q;
            float v0 = acc[mt][nt][0], v1 = acc[mt][nt][1];
            float v2 = acc[mt][nt][2], v3 = acc[mt][nt][3];
            if (epi == EPI_ELU1) {
                v0 = (v0 > 0.f) ? v0 + 1.f : expf(v0);
                v1 = (v1 > 0.f) ? v1 + 1.f : expf(v1);
                v2 = (v2 > 0.f) ? v2 + 1.f : expf(v2);
                v3 = (v3 > 0.f) ? v3 + 1.f : expf(v3);
            } else if (epi == EPI_RELU) {
                v0 = fmaxf(v0, 0.f); v1 = fmaxf(v1, 0.f);
                v2 = fmaxf(v2, 0.f); v3 = fmaxf(v3, 0.f);
            }
            if (outHalf) {
                __half* Ch = (__half*)Cout;
                *(__half2*)(Ch + (size_t)row * N + col)       = __floats2half2_rn(v0, v1);
                *(__half2*)(Ch + (size_t)(row + 8) * N + col) = __floats2half2_rn(v2, v3);
            } else {
                float* Cf = (float*)Cout;
                *(float2*)(Cf + (size_t)row * N + col)       = make_float2(v0, v1);
                *(float2*)(Cf + (size_t)(row + 8) * N + col) = make_float2(v2, v3);
            }
        }
    }
}

// ---------------- Fused GEMM + LayerNorm (BM=64, BN=256, K=256) ----------------
// residual=0: OutH = fp16( LN(A @ B) )      (merge + LN1)
// residual=1: F0 += LN(A @ B); F0h = fp16(F0)   (FFN2 + LN2 + residual)
#define LASW 12
#define LBSW 264

__global__ __launch_bounds__(256, 2) void hgemm_ln_kernel(
    const __half* __restrict__ A, const __half* __restrict__ B,
    __half* __restrict__ OutH,
    float* __restrict__ F0, __half* __restrict__ F0h,
    const float* __restrict__ gam, const float* __restrict__ bet,
    int residual)
{
    __shared__ uint32_t As2[2][64 * LASW];
    __shared__ uint32_t Bs2[2][8 * LBSW];
    __shared__ float sg[256], sb[256];
    __shared__ float srs[64], ssq[64];

    int tid = threadIdx.x;
    int warp = tid >> 5;
    int lane = tid & 31;
    int g = lane >> 2;
    int q = lane & 3;
    int rowBase = blockIdx.x * 64;
    int wm0 = (warp >> 2) * 32;     // 2 warps in M
    int wn0 = (warp & 3) * 64;      // 4 warps in N
    const int NS = 16;              // K = 256

    sg[tid] = gam[tid];
    sb[tid] = bet[tid];
    if (tid < 64) { srs[tid] = 0.0f; ssq[tid] = 0.0f; }

    float acc[2][8][4];
#pragma unroll
    for (int mt = 0; mt < 2; mt++)
#pragma unroll
        for (int nt = 0; nt < 8; nt++)
#pragma unroll
            for (int r = 0; r < 4; r++) acc[mt][nt][r] = 0.0f;

    // A: 128 chunks (64 rows x 2): only tid<128 participate
    int aRow = tid >> 1, aJ = tid & 1;
    // B: 512 chunks (8 kpair rows x 64): all threads x2
    int bR0 = tid >> 6,        bC0 = (tid & 63) << 2;
    int bR1 = (tid + 256) >> 6, bC1 = bC0;

    auto issue = [&](int s, int buf) {
        int k0 = s << 4;
        if (tid < 128)
            cp16(&As2[buf][aRow * LASW + aJ * 4],
                 A + (size_t)(rowBase + aRow) * 256 + k0 + aJ * 8);
        const uint32_t* Bw = (const uint32_t*)B;
        cp16(&Bs2[buf][bR0 * LBSW + bC0], Bw + (size_t)(s * 8 + bR0) * 256 + bC0);
        cp16(&Bs2[buf][bR1 * LBSW + bC1], Bw + (size_t)(s * 8 + bR1) * 256 + bC1);
    };

    issue(0, 0);
    asm volatile("cp.async.commit_group;\n");

    int buf = 0;
    for (int s = 0; s < NS; s++) {
        if (s + 1 < NS) {
            issue(s + 1, buf ^ 1);
            asm volatile("cp.async.commit_group;\n");
            asm volatile("cp.async.wait_group 1;\n");
        } else {
            asm volatile("cp.async.wait_group 0;\n");
        }
        __syncthreads();

        const uint32_t* AsB = As2[buf];
        const uint32_t* BsB = Bs2[buf];
        uint32_t af[2][4];
#pragma unroll
        for (int mt = 0; mt < 2; mt++) {
            int m = wm0 + mt * 16;
            af[mt][0] = AsB[(m + g    ) * LASW + q    ];
            af[mt][1] = AsB[(m + g + 8) * LASW + q    ];
            af[mt][2] = AsB[(m + g    ) * LASW + q + 4];
            af[mt][3] = AsB[(m + g + 8) * LASW + q + 4];
        }
        uint32_t bf[8][2];
#pragma unroll
        for (int nt = 0; nt < 8; nt++) {
            int n = wn0 + nt * 8 + g;
            bf[nt][0] = BsB[q       * LBSW + n];
            bf[nt][1] = BsB[(q + 4) * LBSW + n];
        }
#pragma unroll
        for (int mt = 0; mt < 2; mt++)
#pragma unroll
            for (int nt = 0; nt < 8; nt++) {
                asm volatile(
                    "mma.sync.aligned.m16n8k16.row.col.f32.f16.f16.f32 "
                    "{%0,%1,%2,%3}, {%4,%5,%6,%7}, {%8,%9}, {%0,%1,%2,%3};\n"
                    : "+f"(acc[mt][nt][0]), "+f"(acc[mt][nt][1]),
                      "+f"(acc[mt][nt][2]), "+f"(acc[mt][nt][3])
                    : "r"(af[mt][0]), "r"(af[mt][1]), "r"(af[mt][2]), "r"(af[mt][3]),
                      "r"(bf[nt][0]), "r"(bf[nt][1]));
            }
        buf ^= 1;
        __syncthreads();
    }

    // ---- LayerNorm epilogue ----
    // accumulate per-row sum and sumsq: quad reduce (same row within quad), then SMEM atomics
#pragma unroll
    for (int mt = 0; mt < 2; mt++) {
#pragma unroll
        for (int hr = 0; hr < 2; hr++) {
            int rl = wm0 + mt * 16 + hr * 8 + g;
            float s1 = 0.0f, s2 = 0.0f;
#pragma unroll
            for (int nt = 0; nt < 8; nt++) {
                float v0 = acc[mt][nt][hr * 2], v1 = acc[mt][nt][hr * 2 + 1];
                s1 += v0 + v1;
                s2 += v0 * v0 + v1 * v1;
            }
            s1 += __shfl_xor_sync(0xffffffffu, s1, 1);
            s1 += __shfl_xor_sync(0xffffffffu, s1, 2);
            s2 += __shfl_xor_sync(0xffffffffu, s2, 1);
            s2 += __shfl_xor_sync(0xffffffffu, s2, 2);
            if (q == 0) {
                atomicAdd(&srs[rl], s1);
                atomicAdd(&ssq[rl], s2);
            }
        }
    }
    __syncthreads();

#pragma unroll
    for (int mt = 0; mt < 2; mt++) {
#pragma unroll
        for (int hr = 0; hr < 2; hr++) {
            int rl = wm0 + mt * 16 + hr * 8 + g;
            int row = rowBase + rl;
            float mu = srs[rl] * (1.0f / 256.0f);
            float var = ssq[rl] * (1.0f / 256.0f) - mu * mu;
            float rstd = rsqrtf(var + 1e-5f);
#pragma unroll
            for (int nt = 0; nt < 8; nt++) {
                int col = wn0 + nt * 8 + 2 * q;
                float v0 = (acc[mt][nt][hr * 2]     - mu) * rstd * sg[col]     + sb[col];
                float v1 = (acc[mt][nt][hr * 2 + 1] - mu) * rstd * sg[col + 1] + sb[col + 1];
                size_t o = (size_t)row * 256 + col;
                if (residual) {
                    float2 f = *(float2*)(F0 + o);
                    f.x += v0; f.y += v1;
                    *(float2*)(F0 + o) = f;
                    *(__half2*)(F0h + o) = __floats2half2_rn(f.x, f.y);
                } else {
                    *(__half2*)(OutH + o) = __floats2half2_rn(v0, v1);
                }
            }
        }
    }
}

// ---------------- KV = sum_s K[s,d]*v[s,e], Ksum per (n,h), fp16 inputs ----------------
#define KV_CHUNKS 20
#define KV_SC (LL / KV_CHUNKS)
__global__ void kv_reduce_kernel(const __half* __restrict__ Kb, const __half* __restrict__ Vb,
                                 float* __restrict__ KV, float* __restrict__ KS) {
    int nh = blockIdx.x;
    int n = nh >> 3, h = nh & 7;
    int t = threadIdx.x;
    int d = t & 31;
    int eg = t >> 5;
    int s0 = blockIdx.y * KV_SC;
    float a0 = 0, a1 = 0, a2 = 0, a3 = 0, ks = 0;
    for (int s = s0; s < s0 + KV_SC; s++) {
        size_t base = ((size_t)(n * LL + s) * NHD + h) * HDD;
        float kd = __half2float(Kb[base + d]);
        const __half2* vp = (const __half2*)(Vb + base + eg * 4);
        float2 f0 = __half22float2(vp[0]);
        float2 f1 = __half22float2(vp[1]);
        a0 = fmaf(kd, f0.x, a0);
        a1 = fmaf(kd, f0.y, a1);
        a2 = fmaf(kd, f1.x, a2);
        a3 = fmaf(kd, f1.y, a3);
        ks += kd;
    }
    float* kvp = KV + ((size_t)nh * HDD + d) * HDD + eg * 4;
    atomicAdd(kvp + 0, a0);
    atomicAdd(kvp + 1, a1);
    atomicAdd(kvp + 2, a2);
    atomicAdd(kvp + 3, a3);
    if (eg == 0) atomicAdd(KS + nh * HDD + d, ks);
}

// ---------------- out = (Q.KV[:,e]) / (Q.Ksum + eps); fp16 in/out (in-place) ----------------
#define AT_CHUNKS 40
#define AT_RPB (LL / AT_CHUNKS)
__global__ void attn_apply_kernel(__half* __restrict__ Qb, const float* __restrict__ KV,
                                  const float* __restrict__ KS) {
    __shared__ float kvs[32][33];
    __shared__ float kss[32];
    int n = blockIdx.z, h = blockIdx.y;
    int nh = n * NHD + h;
    int t = threadIdx.x, lane = t & 31, w = t >> 5;
    for (int i = t; i < 1024; i += 256) kvs[i >> 5][i & 31] = KV[(size_t)nh * 1024 + i];
    if (t < 32) kss[t] = KS[nh * 32 + t];
    __syncthreads();
    int l0 = blockIdx.x * AT_RPB + w * (AT_RPB / 8);
    for (int r = 0; r < AT_RPB / 8; r++) {
        int l = l0 + r;
        size_t base = ((size_t)(n * LL + l) * NHD + h) * HDD;
        float qd = __half2float(Qb[base + lane]);
        float zs = qd * kss[lane];
#pragma unroll
        for (int o = 16; o; o >>= 1) zs += __shfl_xor_sync(0xffffffffu, zs, o);
        float z = 1.0f / (zs + 1e-6f);
        float acc = 0.0f;
#pragma unroll
        for (int d = 0; d < 32; d++) {
            float qv = __shfl_sync(0xffffffffu, qd, d);
            acc = fmaf(qv, kvs[d][lane], acc);
        }
        Qb[base + lane] = __float2half_rn(acc * z);
    }
}

// ---------------- launch ----------------
extern "C" void kernel_launch(void* const* d_in, const int* in_sizes, int n_in,
                              void* d_out, int out_size) {
    const float* feat0 = (const float*)d_in[0];
    const float* feat1 = (const float*)d_in[1];
    const float* Wq = (const float*)d_in[2];
    const float* Wk = (const float*)d_in[3];
    const float* Wv = (const float*)d_in[4];
    const float* Wm = (const float*)d_in[5];
    const float* W1 = (const float*)d_in[6];
    const float* W2 = (const float*)d_in[7];
    const float* g1 = (const float*)d_in[8];
    const float* b1 = (const float*)d_in[9];
    const float* g2 = (const float*)d_in[10];
    const float* b2 = (const float*)d_in[11];

    float *F0, *KV, *KS, *PE;
    __half *F0h, *F1h, *Qh, *Kh, *Vh;
    __half *wQ, *wK, *wV, *wM, *w1p, *w2p;
    cudaGetSymbolAddress((void**)&F0,  g_F0);
    cudaGetSymbolAddress((void**)&KV,  g_KV);
    cudaGetSymbolAddress((void**)&KS,  g_KS);
    cudaGetSymbolAddress((void**)&PE,  g_PE);
    cudaGetSymbolAddress((void**)&F0h, g_F0h);
    cudaGetSymbolAddress((void**)&F1h, g_F1h);
    cudaGetSymbolAddress((void**)&Qh,  g_Qh);
    cudaGetSymbolAddress((void**)&Kh,  g_Kh);
    cudaGetSymbolAddress((void**)&Vh,  g_Vh);
    cudaGetSymbolAddress((void**)&wQ,  g_WqH);
    cudaGetSymbolAddress((void**)&wK,  g_WkH);
    cudaGetSymbolAddress((void**)&wV,  g_WvH);
    cudaGetSymbolAddress((void**)&wM,  g_WmH);
    cudaGetSymbolAddress((void**)&w1p, g_W1H);
    cudaGetSymbolAddress((void**)&w2p, g_W2H);

    weight_prep_kernel<<<(2 * 2 * CD * CD + 255) / 256, 256>>>(Wq, Wk, Wv, Wm, W1, W2);
    pe_precompute_kernel<<<(CD * LL + 255) / 256, 256>>>(PE);

    dim3 tb(32, 8);
    dim3 tg(LL / 32, CD / 32, NB);
    build_pe_kernel<<<tg, tb>>>(feat0, PE, F0, F0h);
    build_pe_kernel<<<tg, tb>>>(feat1, PE, nullptr, F1h);

    dim3 gg(CD / 128, MR / 128);
    const int GLN = MR / 64;   // 1200 CTAs for fused LN GEMMs

    for (int i = 0; i < 2; i++) {
        const __half* wq = wQ + (size_t)i * CD * CD;
        const __half* wk = wK + (size_t)i * CD * CD;
        const __half* wv = wV + (size_t)i * CD * CD;
        const __half* wm = wM + (size_t)i * CD * CD;
        const __half* w1 = w1p + (size_t)i * 2 * CD * CD;
        const __half* w2 = w2p + (size_t)i * CD * CD;

        // projections (fp16 out): q -> Qh, k -> Kh, v -> Vh
        hgemm_kernel<<<gg, 256>>>(F0h, F0h, wq, Qh, MR, CD, CD, CD, EPI_ELU1, 1);
        hgemm_kernel<<<gg, 256>>>(F1h, F1h, wk, Kh, MR, CD, CD, CD, EPI_ELU1, 1);
        hgemm_kernel<<<gg, 256>>>(F1h, F1h, wv, Vh, MR, CD, CD, CD, EPI_NONE, 1);

        cudaMemsetAsync(KV, 0, sizeof(float) * NB * NHD * HDD * HDD, 0);
        cudaMemsetAsync(KS, 0, sizeof(float) * NB * NHD * HDD, 0);
        kv_reduce_kernel<<<dim3(NB * NHD, KV_CHUNKS), 256>>>(Kh, Vh, KV, KS);

        // attention apply in place on Qh
        attn_apply_kernel<<<dim3(AT_CHUNKS, NHD, NB), 256>>>(Qh, KV, KS);

        // merge + LN1 fused: Vh = fp16( LN(Qh @ Wm) )
        hgemm_ln_kernel<<<GLN, 256>>>(Qh, wm, Vh, nullptr, nullptr,
                                      g1 + i * CD, b1 + i * CD, 0);

        // FFN1: relu([F0h|Vh] @ W1) -> Kh (fp16)
        hgemm_kernel<<<gg, 256>>>(F0h, Vh, w1, Kh, MR, 2 * CD, CD, CD, EPI_RELU, 1);

        // FFN2 + LN2 + residual fused: F0 += LN(Kh @ W2); F0h = fp16(F0)
        hgemm_ln_kernel<<<GLN, 256>>>(Kh, w2, nullptr, F0, F0h,
                                      g2 + i * CD, b2 + i * CD, 1);
    }

    unbuild_kernel<<<tg, tb>>>(F0, (float*)d_out);
}